// round 15
// baseline (speedup 1.0000x reference)
#include <cuda_runtime.h>
#include <cuda_bf16.h>
#include <cstdint>

#define HIDDEN 256
#define NNODES 20000
#define NEDGES 320000

typedef unsigned long long u64;

// ---------------- device global scratch (allocation-free rule) ----------------
__device__ __align__(16) float g_h1[NNODES * HIDDEN];     // enc output (fp32)
__device__ __align__(16) __nv_bfloat16 g_x_hi[NNODES * HIDDEN];
__device__ __align__(16) __nv_bfloat16 g_x_lo[NNODES * HIDDEN];
__device__ __align__(16) __nv_bfloat16 g_ag_hi[NNODES * HIDDEN];
__device__ __align__(16) __nv_bfloat16 g_ag_lo[NNODES * HIDDEN];
__device__ __align__(16) __nv_bfloat16 g_h2_hi[NNODES * 2 * HIDDEN];
__device__ __align__(16) __nv_bfloat16 g_h2_lo[NNODES * 2 * HIDDEN];
__device__ __align__(16) __nv_bfloat16 g_We_hi[HIDDEN * HIDDEN];
__device__ __align__(16) __nv_bfloat16 g_We_lo[HIDDEN * HIDDEN];
__device__ __align__(16) __nv_bfloat16 g_W1_hi[2 * HIDDEN * HIDDEN];
__device__ __align__(16) __nv_bfloat16 g_W1_lo[2 * HIDDEN * HIDDEN];
__device__ __align__(16) __nv_bfloat16 g_W2_hi[HIDDEN * 2 * HIDDEN];
__device__ __align__(16) __nv_bfloat16 g_W2_lo[HIDDEN * 2 * HIDDEN];
// sort/aggregate scratch
__device__ __align__(16) int  g_deg[NNODES];
__device__ __align__(16) int  g_cnt[NNODES];
__device__ __align__(16) int  g_off[NNODES];
__device__ __align__(16) int2  g_sorted[NEDGES];          // (src, combo)
__device__ __align__(16) float g_Ctab[10 * HIDDEN];       // 9 combos + selfloop
__device__ __align__(16) unsigned g_maskbits[(NNODES + 31) / 32];
__device__ int g_is64;

// ---------------- host-side stream/event infra (created before main) ----------
static cudaStream_t g_s2;
static cudaEvent_t  g_evFork, g_evJoin;
struct GInit {
    GInit() {
        cudaStreamCreateWithFlags(&g_s2, cudaStreamNonBlocking);
        cudaEventCreateWithFlags(&g_evFork, cudaEventDisableTiming);
        cudaEventCreateWithFlags(&g_evJoin, cudaEventDisableTiming);
    }
};
static GInit g_init;

// ---------------- index dtype helpers ----------------
__device__ __forceinline__ long long load_idx(const void* p, long long i, int is64)
{
    return is64 ? ((const long long*)p)[i] : (long long)((const int*)p)[i];
}

__device__ __forceinline__ uint32_t smem_u32(const void* p) {
    uint32_t a;
    asm("{ .reg .u64 t; cvta.to.shared.u64 t, %1; cvt.u32.u64 %0, t; }"
        : "=r"(a) : "l"(p));
    return a;
}

// cp.async 16B with zero-fill predicate (src-size=0 -> fill zeros)
__device__ __forceinline__ void cp16(uint32_t dst, const void* src, bool pred) {
    int sz = pred ? 16 : 0;
    asm volatile("cp.async.cg.shared.global [%0], [%1], 16, %2;"
                 :: "r"(dst), "l"(src), "r"(sz) : "memory");
}
#define CP_COMMIT() asm volatile("cp.async.commit_group;" ::: "memory")
#define CP_WAIT(n)  asm volatile("cp.async.wait_group %0;" :: "n"(n) : "memory")

// SW128-style swizzle inside an 8KB tile:
__device__ __forceinline__ uint32_t tile_off(int r, int c) {
    uint32_t off = (uint32_t)((r & 63) * 128 + ((r >> 6) << 6) + c);
    return off ^ ((off >> 3) & 0x70);
}

// ---------------- hi/lo split ----------------
__device__ __forceinline__ void split1(float v, __nv_bfloat16& h, __nv_bfloat16& l) {
    h = __float2bfloat16(v);
    l = __float2bfloat16(v - __bfloat162float(h));
}

template <int PRELU>
__global__ __launch_bounds__(256)
void split_f32(const float* __restrict__ in, __nv_bfloat16* __restrict__ hi,
               __nv_bfloat16* __restrict__ lo, int n4, const float* __restrict__ pa)
{
    int i = blockIdx.x * 256 + threadIdx.x;
    if (i >= n4) return;
    float4 v = ((const float4*)in)[i];
    if (PRELU) {
        float a = *pa;
        v.x = v.x >= 0.f ? v.x : a * v.x;
        v.y = v.y >= 0.f ? v.y : a * v.y;
        v.z = v.z >= 0.f ? v.z : a * v.z;
        v.w = v.w >= 0.f ? v.w : a * v.w;
    }
    __nv_bfloat16 h[4], l[4];
    split1(v.x, h[0], l[0]); split1(v.y, h[1], l[1]);
    split1(v.z, h[2], l[2]); split1(v.w, h[3], l[3]);
    ((uint2*)hi)[i] = *(uint2*)h;
    ((uint2*)lo)[i] = *(uint2*)l;
}

// Combined split of the 3 weight matrices (one launch).
__global__ __launch_bounds__(256)
void split_weights(const float* __restrict__ We, const float* __restrict__ W1,
                   const float* __restrict__ W2,
                   __nv_bfloat16* __restrict__ Wehi, __nv_bfloat16* __restrict__ Welo,
                   __nv_bfloat16* __restrict__ W1hi, __nv_bfloat16* __restrict__ W1lo,
                   __nv_bfloat16* __restrict__ W2hi, __nv_bfloat16* __restrict__ W2lo)
{
    int i = blockIdx.x * 256 + threadIdx.x;
    if (i >= 81920) return;
    const float* in; __nv_bfloat16 *hi, *lo; int j;
    if (i < 16384)      { in = We; hi = Wehi; lo = Welo; j = i; }
    else if (i < 49152) { in = W1; hi = W1hi; lo = W1lo; j = i - 16384; }
    else                { in = W2; hi = W2hi; lo = W2lo; j = i - 49152; }
    float4 v = ((const float4*)in)[j];
    __nv_bfloat16 h[4], l[4];
    split1(v.x, h[0], l[0]); split1(v.y, h[1], l[1]);
    split1(v.z, h[2], l[2]); split1(v.w, h[3], l[3]);
    ((uint2*)hi)[j] = *(uint2*)h;
    ((uint2*)lo)[j] = *(uint2*)l;
}

// ---------------- mma.sync helpers ----------------
__device__ __forceinline__ void ldmat4(uint32_t& r0, uint32_t& r1, uint32_t& r2,
                                       uint32_t& r3, uint32_t addr) {
    asm volatile("ldmatrix.sync.aligned.m8n8.x4.shared.b16 {%0,%1,%2,%3}, [%4];"
                 : "=r"(r0), "=r"(r1), "=r"(r2), "=r"(r3) : "r"(addr));
}
__device__ __forceinline__ void mma16816(float& d0, float& d1, float& d2, float& d3,
                                         uint32_t a0, uint32_t a1, uint32_t a2, uint32_t a3,
                                         uint32_t b0, uint32_t b1) {
    asm volatile("mma.sync.aligned.m16n8k16.row.col.f32.bf16.bf16.f32 "
                 "{%0,%1,%2,%3}, {%4,%5,%6,%7}, {%8,%9}, {%0,%1,%2,%3};"
                 : "+f"(d0), "+f"(d1), "+f"(d2), "+f"(d3)
                 : "r"(a0), "r"(a1), "r"(a2), "r"(a3), "r"(b0), "r"(b1));
}

// ---------------------------------------------------------------------------
// bf16 hi/lo GEMM (cp.async 3-stage pipelined, swizzled smem)
// ---------------------------------------------------------------------------
#define TILE_B 8192
#define STG_B  (4 * TILE_B)
#define NSTAGE 3

template <int MODE>
__global__ __launch_bounds__(256)
void gemm_mma(const __nv_bfloat16* __restrict__ Ahi, const __nv_bfloat16* __restrict__ Alo,
              const __nv_bfloat16* __restrict__ Bhi, const __nv_bfloat16* __restrict__ Blo,
              const float* __restrict__ bias, float* __restrict__ Cf,
              __nv_bfloat16* __restrict__ Chi, __nv_bfloat16* __restrict__ Clo,
              int M, int N, int K)
{
    extern __shared__ __align__(1024) char smem[];
    const uint32_t sb = smem_u32(smem);

    const int tid = threadIdx.x, lane = tid & 31, wid = tid >> 5;
    const int wm = wid >> 2, wn = wid & 3;
    const int m0 = blockIdx.y * 128, n0 = blockIdx.x * 128;

    const int ra = lane & 7, mata = lane >> 3;
    const int aRow = ra + (mata & 1) * 8, aCol = (mata >> 1) * 8;

    float d[4][4][4];
#pragma unroll
    for (int i = 0; i < 4; i++)
#pragma unroll
        for (int j = 0; j < 4; j++)
#pragma unroll
            for (int k = 0; k < 4; k++) d[i][j][k] = 0.f;

    const int nchunks = K >> 5;

    auto load_stage = [&](int c, int buf) {
        const int k0c = c << 5;
        const uint32_t st = sb + buf * STG_B;
#pragma unroll
        for (int i = 0; i < 8; i++) {
            int q = tid + 256 * i;
            int tile = q >> 9;
            int rem = q & 511;
            int r = rem >> 2, seg = rem & 3;
            uint32_t dst = st + tile * TILE_B + tile_off(r, seg * 16);
            if (tile < 2) {
                int row = m0 + r;
                bool ok = row < M;
                const __nv_bfloat16* src =
                    (tile ? Alo : Ahi) + (size_t)(ok ? row : 0) * K + k0c + seg * 8;
                cp16(dst, src, ok);
            } else {
                const __nv_bfloat16* src =
                    (tile == 3 ? Blo : Bhi) + (size_t)(n0 + r) * K + k0c + seg * 8;
                cp16(dst, src, true);
            }
        }
        CP_COMMIT();
    };

    load_stage(0, 0);
    if (nchunks > 1) load_stage(1, 1);

    for (int c = 0; c < nchunks; c++) {
        if (c + 1 < nchunks) { CP_WAIT(1); } else { CP_WAIT(0); }
        __syncthreads();
        if (c + 2 < nchunks) load_stage(c + 2, (c + 2) % NSTAGE);

        const uint32_t st = sb + (c % NSTAGE) * STG_B;
        const uint32_t sAhi = st, sAlo = st + TILE_B;
        const uint32_t sBhi = st + 2 * TILE_B, sBlo = st + 3 * TILE_B;

#pragma unroll
        for (int ks = 0; ks < 2; ks++) {
            const int kk = ks * 16;
            const int cb = (kk + aCol) * 2;

            uint32_t a[4][4];
#pragma unroll
            for (int mf = 0; mf < 4; mf++)
                ldmat4(a[mf][0], a[mf][1], a[mf][2], a[mf][3],
                       sAhi + tile_off(wm * 64 + mf * 16 + aRow, cb));
            uint32_t bh[2][4], bl[2][4];
#pragma unroll
            for (int bf = 0; bf < 2; bf++) {
                ldmat4(bh[bf][0], bh[bf][1], bh[bf][2], bh[bf][3],
                       sBhi + tile_off(wn * 32 + bf * 16 + aRow, cb));
                ldmat4(bl[bf][0], bl[bf][1], bl[bf][2], bl[bf][3],
                       sBlo + tile_off(wn * 32 + bf * 16 + aRow, cb));
            }
#pragma unroll
            for (int mf = 0; mf < 4; mf++)
#pragma unroll
                for (int nf = 0; nf < 4; nf++) {
                    mma16816(d[mf][nf][0], d[mf][nf][1], d[mf][nf][2], d[mf][nf][3],
                             a[mf][0], a[mf][1], a[mf][2], a[mf][3],
                             bh[nf >> 1][(nf & 1)], bh[nf >> 1][(nf & 1) + 2]);
                    mma16816(d[mf][nf][0], d[mf][nf][1], d[mf][nf][2], d[mf][nf][3],
                             a[mf][0], a[mf][1], a[mf][2], a[mf][3],
                             bl[nf >> 1][(nf & 1)], bl[nf >> 1][(nf & 1) + 2]);
                }
#pragma unroll
            for (int mf = 0; mf < 4; mf++)
                ldmat4(a[mf][0], a[mf][1], a[mf][2], a[mf][3],
                       sAlo + tile_off(wm * 64 + mf * 16 + aRow, cb));
#pragma unroll
            for (int mf = 0; mf < 4; mf++)
#pragma unroll
                for (int nf = 0; nf < 4; nf++)
                    mma16816(d[mf][nf][0], d[mf][nf][1], d[mf][nf][2], d[mf][nf][3],
                             a[mf][0], a[mf][1], a[mf][2], a[mf][3],
                             bh[nf >> 1][(nf & 1)], bh[nf >> 1][(nf & 1) + 2]);
        }
    }

#pragma unroll
    for (int mf = 0; mf < 4; mf++) {
        int row = m0 + wm * 64 + mf * 16 + (lane >> 2);
#pragma unroll
        for (int half = 0; half < 2; half++) {
            int r = row + half * 8;
            if (r >= M) continue;
#pragma unroll
            for (int nf = 0; nf < 4; nf++) {
                int col = n0 + wn * 32 + nf * 8 + (lane & 3) * 2;
                float v0 = d[mf][nf][half * 2], v1 = d[mf][nf][half * 2 + 1];
                if (MODE >= 1) {
                    v0 += __ldg(bias + col);
                    v1 += __ldg(bias + col + 1);
                }
                if (MODE == 1) {
                    v0 = fmaxf(v0, 0.f); v1 = fmaxf(v1, 0.f);
                    __nv_bfloat16 h0, l0, h1, l1;
                    split1(v0, h0, l0); split1(v1, h1, l1);
                    __nv_bfloat162 hh; hh.x = h0; hh.y = h1;
                    __nv_bfloat162 ll; ll.x = l0; ll.y = l1;
                    *(__nv_bfloat162*)(Chi + (size_t)r * N + col) = hh;
                    *(__nv_bfloat162*)(Clo + (size_t)r * N + col) = ll;
                } else {
                    *(float2*)(Cf + (size_t)r * N + col) = make_float2(v0, v1);
                }
            }
        }
    }
}

// ---------------- graph part: sorted aggregation ----------------
// zero counters + bitmap + build Ctab + detect idx dtype, one launch
__global__ void prep_misc(int* __restrict__ deg, int* __restrict__ cnt,
                          const float* __restrict__ E1, const float* __restrict__ E2,
                          float* __restrict__ Ctab, const int* __restrict__ ei_words,
                          unsigned* __restrict__ maskbits)
{
    int i = blockIdx.x * 256 + threadIdx.x;
    if (i == 0) {
        int is64 = 1;
        for (int k = 1; k < 64; k += 2)
            if (ei_words[k] != 0) { is64 = 0; break; }
        g_is64 = is64;
    }
    if (i < NNODES) { deg[i] = 0; cnt[i] = 0; }
    if (i < (NNODES + 31) / 32) maskbits[i] = 0u;
    if (i < 10 * HIDDEN) {
        int c = i / HIDDEN, dd = i % HIDDEN;
        int r1 = (c == 9) ? 4 : (c % 3);
        int r2 = (c == 9) ? 0 : (c / 3);
        Ctab[i] = E1[r1 * HIDDEN + dd] + E2[r2 * HIDDEN + dd];
    }
}

__global__ void set_maskbits(const void* __restrict__ mask, unsigned* __restrict__ bits,
                             int nmask)
{
    int i = blockIdx.x * 256 + threadIdx.x;
    if (i >= nmask) return;
    int r = (int)load_idx(mask, i, g_is64);
    atomicOr(&bits[r >> 5], 1u << (r & 31));
}

__global__ void hist_dst(const void* __restrict__ ei, int* __restrict__ deg)
{
    int e = blockIdx.x * 256 + threadIdx.x;
    if (e >= NEDGES) return;
    int dst = (int)load_idx(ei, (long long)NEDGES + e, g_is64);
    atomicAdd(&deg[dst], 1);
}

// Exclusive prefix scan over NNODES ints (= 5000 int4). Single block, 1024 thr.
__global__ __launch_bounds__(1024)
void scan_deg(const int4* __restrict__ deg4, int4* __restrict__ off4)
{
    __shared__ int wsum[32];
    const int t = threadIdx.x, lane = t & 31, w = t >> 5;
    const int base = t * 5;
    int4 v[5];
    int sum = 0;
#pragma unroll
    for (int i = 0; i < 5; i++) {
        int idx = base + i;
        v[i] = (idx < 5000) ? deg4[idx] : make_int4(0, 0, 0, 0);
        sum += v[i].x + v[i].y + v[i].z + v[i].w;
    }
    int s = sum;
#pragma unroll
    for (int dlt = 1; dlt < 32; dlt <<= 1) {
        int o = __shfl_up_sync(0xffffffff, s, dlt);
        if (lane >= dlt) s += o;
    }
    if (lane == 31) wsum[w] = s;
    __syncthreads();
    if (w == 0) {
        int ws = (t < 32) ? wsum[t] : 0;
#pragma unroll
        for (int dlt = 1; dlt < 32; dlt <<= 1) {
            int o = __shfl_up_sync(0xffffffff, ws, dlt);
            if (lane >= dlt) ws += o;
        }
        if (t < 32) wsum[t] = ws;
    }
    __syncthreads();
    int pre = s - sum + (w > 0 ? wsum[w - 1] : 0);
#pragma unroll
    for (int i = 0; i < 5; i++) {
        int idx = base + i;
        if (idx < 5000) {
            int4 o;
            o.x = pre;            pre += v[i].x;
            o.y = pre;            pre += v[i].y;
            o.z = pre;            pre += v[i].z;
            o.w = pre;            pre += v[i].w;
            off4[idx] = o;
        }
    }
}

__global__ void scatter_edges(const void* __restrict__ ei, const void* __restrict__ ea,
                              const int* __restrict__ off, int* __restrict__ cnt,
                              int2* __restrict__ sorted)
{
    int e = blockIdx.x * 256 + threadIdx.x;
    if (e >= NEDGES) return;
    const int is64 = g_is64;
    int src = (int)load_idx(ei, e, is64);
    int dst = (int)load_idx(ei, (long long)NEDGES + e, is64);
    int a0  = (int)load_idx(ea, 2LL * e, is64);
    int a1  = (int)load_idx(ea, 2LL * e + 1, is64);
    int pos = off[dst] + atomicAdd(&cnt[dst], 1);
    sorted[pos] = make_int2(src, a0 + 3 * a1);
}

// One 64-thread block per node: register accumulation + mask-predicated h1 terms
// + fused bf16 hi/lo split. (Masked rows contribute 0 for the h1 part only.)
__global__ __launch_bounds__(64)
void aggregate(const float* __restrict__ h1, const int2* __restrict__ sorted,
               const int* __restrict__ off, const float* __restrict__ Ctab,
               const unsigned* __restrict__ bits,
               __nv_bfloat16* __restrict__ aghi, __nv_bfloat16* __restrict__ aglo)
{
    const int n = blockIdx.x;
    const int t = threadIdx.x;
    const int s0 = off[n];
    const int s1 = (n == NNODES - 1) ? NEDGES : off[n + 1];

    float selfS = ((bits[n >> 5] >> (n & 31)) & 1u) ? 0.f : 1.f;
    float4 hv = ((const float4*)(h1 + (size_t)n * HIDDEN))[t];
    float4 cs  = ((const float4*)(Ctab + 9 * HIDDEN))[t];
    float4 acc;
    acc.x = fmaf(hv.x, selfS, cs.x);
    acc.y = fmaf(hv.y, selfS, cs.y);
    acc.z = fmaf(hv.z, selfS, cs.z);
    acc.w = fmaf(hv.w, selfS, cs.w);

    int p = s0;
    for (; p + 1 < s1; p += 2) {
        int2 r0 = __ldg(&sorted[p]);
        int2 r1 = __ldg(&sorted[p + 1]);
        float sc0 = ((bits[r0.x >> 5] >> (r0.x & 31)) & 1u) ? 0.f : 1.f;
        float sc1 = ((bits[r1.x >> 5] >> (r1.x & 31)) & 1u) ? 0.f : 1.f;
        float4 x0 = ((const float4*)(h1 + (size_t)r0.x * HIDDEN))[t];
        float4 c0 = ((const float4*)(Ctab + r0.y * HIDDEN))[t];
        float4 x1 = ((const float4*)(h1 + (size_t)r1.x * HIDDEN))[t];
        float4 c1 = ((const float4*)(Ctab + r1.y * HIDDEN))[t];
        acc.x += fmaf(x0.x, sc0, c0.x); acc.y += fmaf(x0.y, sc0, c0.y);
        acc.z += fmaf(x0.z, sc0, c0.z); acc.w += fmaf(x0.w, sc0, c0.w);
        acc.x += fmaf(x1.x, sc1, c1.x); acc.y += fmaf(x1.y, sc1, c1.y);
        acc.z += fmaf(x1.z, sc1, c1.z); acc.w += fmaf(x1.w, sc1, c1.w);
    }
    if (p < s1) {
        int2 rec = __ldg(&sorted[p]);
        float sc = ((bits[rec.x >> 5] >> (rec.x & 31)) & 1u) ? 0.f : 1.f;
        float4 xv = ((const float4*)(h1 + (size_t)rec.x * HIDDEN))[t];
        float4 cv = ((const float4*)(Ctab + rec.y * HIDDEN))[t];
        acc.x += fmaf(xv.x, sc, cv.x); acc.y += fmaf(xv.y, sc, cv.y);
        acc.z += fmaf(xv.z, sc, cv.z); acc.w += fmaf(xv.w, sc, cv.w);
    }

    __nv_bfloat16 h[4], l[4];
    split1(acc.x, h[0], l[0]); split1(acc.y, h[1], l[1]);
    split1(acc.z, h[2], l[2]); split1(acc.w, h[3], l[3]);
    ((uint2*)(aghi + (size_t)n * HIDDEN))[t] = *(uint2*)h;
    ((uint2*)(aglo + (size_t)n * HIDDEN))[t] = *(uint2*)l;
}

extern "C" void kernel_launch(void* const* d_in, const int* in_sizes, int n_in,
                              void* d_out, int out_size)
{
    const float* x     = (const float*)d_in[0];
    const void*  ei    = d_in[1];
    const void*  ea    = d_in[2];
    const void*  mask  = d_in[3];
    const float* pa    = (const float*)d_in[4];
    const float* W_enc = (const float*)d_in[5];
    const float* E1    = (const float*)d_in[6];
    const float* E2    = (const float*)d_in[7];
    const float* W1    = (const float*)d_in[8];
    const float* b1    = (const float*)d_in[9];
    const float* W2    = (const float*)d_in[10];
    const float* b2    = (const float*)d_in[11];
    float* out = (float*)d_out;

    float *h1, *Ctab;
    int *deg, *cnt, *off;
    int2 *sorted;
    unsigned *maskbits;
    __nv_bfloat16 *xhi, *xlo, *aghi, *aglo, *h2hi, *h2lo;
    __nv_bfloat16 *Wehi, *Welo, *W1hi, *W1lo, *W2hi, *W2lo;
    cudaGetSymbolAddress((void**)&h1,     g_h1);
    cudaGetSymbolAddress((void**)&Ctab,   g_Ctab);
    cudaGetSymbolAddress((void**)&deg,    g_deg);
    cudaGetSymbolAddress((void**)&cnt,    g_cnt);
    cudaGetSymbolAddress((void**)&off,    g_off);
    cudaGetSymbolAddress((void**)&sorted, g_sorted);
    cudaGetSymbolAddress((void**)&maskbits, g_maskbits);
    cudaGetSymbolAddress((void**)&xhi,  g_x_hi);
    cudaGetSymbolAddress((void**)&xlo,  g_x_lo);
    cudaGetSymbolAddress((void**)&aghi, g_ag_hi);
    cudaGetSymbolAddress((void**)&aglo, g_ag_lo);
    cudaGetSymbolAddress((void**)&h2hi, g_h2_hi);
    cudaGetSymbolAddress((void**)&h2lo, g_h2_lo);
    cudaGetSymbolAddress((void**)&Wehi, g_We_hi);
    cudaGetSymbolAddress((void**)&Welo, g_We_lo);
    cudaGetSymbolAddress((void**)&W1hi, g_W1_hi);
    cudaGetSymbolAddress((void**)&W1lo, g_W1_lo);
    cudaGetSymbolAddress((void**)&W2hi, g_W2_hi);
    cudaGetSymbolAddress((void**)&W2lo, g_W2_lo);

    const int SMEM_SZ = NSTAGE * STG_B;   // 98304
    cudaFuncSetAttribute(gemm_mma<0>, cudaFuncAttributeMaxDynamicSharedMemorySize, SMEM_SZ);
    cudaFuncSetAttribute(gemm_mma<1>, cudaFuncAttributeMaxDynamicSharedMemorySize, SMEM_SZ);
    cudaFuncSetAttribute(gemm_mma<2>, cudaFuncAttributeMaxDynamicSharedMemorySize, SMEM_SZ);

    const int MB = (NNODES + 127) / 128;   // 157
    const int EB = (NEDGES + 255) / 256;   // 1250

    // ---- fork: graph-prep chain + weight split on side stream ----
    cudaEventRecord(g_evFork, 0);
    cudaStreamWaitEvent(g_s2, g_evFork, 0);
    prep_misc<<<(NNODES + 255) / 256, 256, 0, g_s2>>>(deg, cnt, E1, E2, Ctab,
                                                      (const int*)ei, maskbits);
    set_maskbits<<<(2000 + 255) / 256, 256, 0, g_s2>>>(mask, maskbits, 2000);
    hist_dst<<<EB, 256, 0, g_s2>>>(ei, deg);
    scan_deg<<<1, 1024, 0, g_s2>>>((const int4*)deg, (int4*)off);
    scatter_edges<<<EB, 256, 0, g_s2>>>(ei, ea, off, cnt, sorted);
    split_weights<<<(81920 + 255) / 256, 256, 0, g_s2>>>(W_enc, W1, W2,
                                                Wehi, Welo, W1hi, W1lo, W2hi, W2lo);
    cudaEventRecord(g_evJoin, g_s2);

    // ---- main stream: split_x + GEMM1 (GEMM1 needs weights -> join first) ----
    split_f32<1><<<(NNODES * HIDDEN / 4 + 255) / 256, 256>>>(x, xhi, xlo, NNODES * HIDDEN / 4, pa);
    cudaStreamWaitEvent(0, g_evJoin, 0);
    gemm_mma<0><<<dim3(HIDDEN / 128, MB), 256, SMEM_SZ>>>(
        xhi, xlo, Wehi, Welo, nullptr, h1, nullptr, nullptr, NNODES, HIDDEN, HIDDEN);

    // ---- aggregation (mask fused) + GIN MLP ----
    aggregate<<<NNODES, 64>>>(h1, sorted, off, Ctab, maskbits, aghi, aglo);

    gemm_mma<1><<<dim3(2 * HIDDEN / 128, MB), 256, SMEM_SZ>>>(
        aghi, aglo, W1hi, W1lo, b1, nullptr, h2hi, h2lo, NNODES, 2 * HIDDEN, HIDDEN);

    gemm_mma<2><<<dim3(HIDDEN / 128, MB), 256, SMEM_SZ>>>(
        h2hi, h2lo, W2hi, W2lo, b2, out, nullptr, nullptr, NNODES, HIDDEN, 2 * HIDDEN);
}

// round 16
// speedup vs baseline: 1.5043x; 1.5043x over previous
#include <cuda_runtime.h>
#include <cuda_bf16.h>
#include <cstdint>

#define HIDDEN 256
#define NNODES 20000
#define NEDGES 320000

typedef unsigned long long u64;

// ---------------- device global scratch (allocation-free rule) ----------------
__device__ __align__(16) float g_h1[NNODES * HIDDEN];     // enc output (fp32)
__device__ __align__(16) __nv_bfloat16 g_x_hi[NNODES * HIDDEN];
__device__ __align__(16) __nv_bfloat16 g_x_lo[NNODES * HIDDEN];
__device__ __align__(16) __nv_bfloat16 g_ag_hi[NNODES * HIDDEN];
__device__ __align__(16) __nv_bfloat16 g_ag_lo[NNODES * HIDDEN];
__device__ __align__(16) __nv_bfloat16 g_h2_hi[NNODES * 2 * HIDDEN];
__device__ __align__(16) __nv_bfloat16 g_h2_lo[NNODES * 2 * HIDDEN];
__device__ __align__(16) __nv_bfloat16 g_We_hi[HIDDEN * HIDDEN];
__device__ __align__(16) __nv_bfloat16 g_We_lo[HIDDEN * HIDDEN];
__device__ __align__(16) __nv_bfloat16 g_W1_hi[2 * HIDDEN * HIDDEN];
__device__ __align__(16) __nv_bfloat16 g_W1_lo[2 * HIDDEN * HIDDEN];
__device__ __align__(16) __nv_bfloat16 g_W2_hi[HIDDEN * 2 * HIDDEN];
__device__ __align__(16) __nv_bfloat16 g_W2_lo[HIDDEN * 2 * HIDDEN];
// sort/aggregate scratch
__device__ __align__(16) int  g_deg[NNODES];
__device__ __align__(16) int  g_cnt[NNODES];
__device__ __align__(16) int  g_off[NNODES];
__device__ __align__(16) int2  g_sorted[NEDGES];          // (src, combo)
__device__ __align__(16) float g_Ctab[10 * HIDDEN];       // 9 combos + selfloop
__device__ __align__(16) unsigned g_maskbits[(NNODES + 31) / 32];
__device__ int g_is64;

// ---------------- host-side stream/event infra (created before main) ----------
static cudaStream_t g_s2;
static cudaEvent_t  g_evFork, g_evJoin;
struct GInit {
    GInit() {
        cudaStreamCreateWithFlags(&g_s2, cudaStreamNonBlocking);
        cudaEventCreateWithFlags(&g_evFork, cudaEventDisableTiming);
        cudaEventCreateWithFlags(&g_evJoin, cudaEventDisableTiming);
    }
};
static GInit g_init;

// ---------------- index dtype helpers ----------------
__device__ __forceinline__ long long load_idx(const void* p, long long i, int is64)
{
    return is64 ? ((const long long*)p)[i] : (long long)((const int*)p)[i];
}

__device__ __forceinline__ uint32_t smem_u32(const void* p) {
    uint32_t a;
    asm("{ .reg .u64 t; cvta.to.shared.u64 t, %1; cvt.u32.u64 %0, t; }"
        : "=r"(a) : "l"(p));
    return a;
}

// cp.async 16B with zero-fill predicate (src-size=0 -> fill zeros)
__device__ __forceinline__ void cp16(uint32_t dst, const void* src, bool pred) {
    int sz = pred ? 16 : 0;
    asm volatile("cp.async.cg.shared.global [%0], [%1], 16, %2;"
                 :: "r"(dst), "l"(src), "r"(sz) : "memory");
}
#define CP_COMMIT() asm volatile("cp.async.commit_group;" ::: "memory")
#define CP_WAIT(n)  asm volatile("cp.async.wait_group %0;" :: "n"(n) : "memory")

// SW128-style swizzle inside an 8KB tile:
__device__ __forceinline__ uint32_t tile_off(int r, int c) {
    uint32_t off = (uint32_t)((r & 63) * 128 + ((r >> 6) << 6) + c);
    return off ^ ((off >> 3) & 0x70);
}

// ---------------- hi/lo split ----------------
__device__ __forceinline__ void split1(float v, __nv_bfloat16& h, __nv_bfloat16& l) {
    h = __float2bfloat16(v);
    l = __float2bfloat16(v - __bfloat162float(h));
}

template <int PRELU>
__global__ __launch_bounds__(256)
void split_f32(const float* __restrict__ in, __nv_bfloat16* __restrict__ hi,
               __nv_bfloat16* __restrict__ lo, int n4, const float* __restrict__ pa)
{
    int i = blockIdx.x * 256 + threadIdx.x;
    if (i >= n4) return;
    float4 v = ((const float4*)in)[i];
    if (PRELU) {
        float a = *pa;
        v.x = v.x >= 0.f ? v.x : a * v.x;
        v.y = v.y >= 0.f ? v.y : a * v.y;
        v.z = v.z >= 0.f ? v.z : a * v.z;
        v.w = v.w >= 0.f ? v.w : a * v.w;
    }
    __nv_bfloat16 h[4], l[4];
    split1(v.x, h[0], l[0]); split1(v.y, h[1], l[1]);
    split1(v.z, h[2], l[2]); split1(v.w, h[3], l[3]);
    ((uint2*)hi)[i] = *(uint2*)h;
    ((uint2*)lo)[i] = *(uint2*)l;
}

// Combined split of the 3 weight matrices (one launch).
__global__ __launch_bounds__(256)
void split_weights(const float* __restrict__ We, const float* __restrict__ W1,
                   const float* __restrict__ W2,
                   __nv_bfloat16* __restrict__ Wehi, __nv_bfloat16* __restrict__ Welo,
                   __nv_bfloat16* __restrict__ W1hi, __nv_bfloat16* __restrict__ W1lo,
                   __nv_bfloat16* __restrict__ W2hi, __nv_bfloat16* __restrict__ W2lo)
{
    int i = blockIdx.x * 256 + threadIdx.x;
    if (i >= 81920) return;
    const float* in; __nv_bfloat16 *hi, *lo; int j;
    if (i < 16384)      { in = We; hi = Wehi; lo = Welo; j = i; }
    else if (i < 49152) { in = W1; hi = W1hi; lo = W1lo; j = i - 16384; }
    else                { in = W2; hi = W2hi; lo = W2lo; j = i - 49152; }
    float4 v = ((const float4*)in)[j];
    __nv_bfloat16 h[4], l[4];
    split1(v.x, h[0], l[0]); split1(v.y, h[1], l[1]);
    split1(v.z, h[2], l[2]); split1(v.w, h[3], l[3]);
    ((uint2*)hi)[j] = *(uint2*)h;
    ((uint2*)lo)[j] = *(uint2*)l;
}

// ---------------- mma.sync helpers ----------------
__device__ __forceinline__ void ldmat4(uint32_t& r0, uint32_t& r1, uint32_t& r2,
                                       uint32_t& r3, uint32_t addr) {
    asm volatile("ldmatrix.sync.aligned.m8n8.x4.shared.b16 {%0,%1,%2,%3}, [%4];"
                 : "=r"(r0), "=r"(r1), "=r"(r2), "=r"(r3) : "r"(addr));
}
__device__ __forceinline__ void mma16816(float& d0, float& d1, float& d2, float& d3,
                                         uint32_t a0, uint32_t a1, uint32_t a2, uint32_t a3,
                                         uint32_t b0, uint32_t b1) {
    asm volatile("mma.sync.aligned.m16n8k16.row.col.f32.bf16.bf16.f32 "
                 "{%0,%1,%2,%3}, {%4,%5,%6,%7}, {%8,%9}, {%0,%1,%2,%3};"
                 : "+f"(d0), "+f"(d1), "+f"(d2), "+f"(d3)
                 : "r"(a0), "r"(a1), "r"(a2), "r"(a3), "r"(b0), "r"(b1));
}

// ---------------------------------------------------------------------------
// bf16 hi/lo GEMM (cp.async double-buffered, swizzled smem; 2 CTAs/SM)
// ---------------------------------------------------------------------------
#define TILE_B 8192
#define STG_B  (4 * TILE_B)

template <int MODE>
__global__ __launch_bounds__(256)
void gemm_mma(const __nv_bfloat16* __restrict__ Ahi, const __nv_bfloat16* __restrict__ Alo,
              const __nv_bfloat16* __restrict__ Bhi, const __nv_bfloat16* __restrict__ Blo,
              const float* __restrict__ bias, float* __restrict__ Cf,
              __nv_bfloat16* __restrict__ Chi, __nv_bfloat16* __restrict__ Clo,
              int M, int N, int K)
{
    extern __shared__ __align__(1024) char smem[];
    const uint32_t sb = smem_u32(smem);

    const int tid = threadIdx.x, lane = tid & 31, wid = tid >> 5;
    const int wm = wid >> 2, wn = wid & 3;
    const int m0 = blockIdx.y * 128, n0 = blockIdx.x * 128;

    const int ra = lane & 7, mata = lane >> 3;
    const int aRow = ra + (mata & 1) * 8, aCol = (mata >> 1) * 8;

    float d[4][4][4];
#pragma unroll
    for (int i = 0; i < 4; i++)
#pragma unroll
        for (int j = 0; j < 4; j++)
#pragma unroll
            for (int k = 0; k < 4; k++) d[i][j][k] = 0.f;

    const int nchunks = K >> 5;

    auto load_stage = [&](int c, int buf) {
        const int k0c = c << 5;
        const uint32_t st = sb + buf * STG_B;
#pragma unroll
        for (int i = 0; i < 8; i++) {
            int q = tid + 256 * i;
            int tile = q >> 9;
            int rem = q & 511;
            int r = rem >> 2, seg = rem & 3;
            uint32_t dst = st + tile * TILE_B + tile_off(r, seg * 16);
            if (tile < 2) {
                int row = m0 + r;
                bool ok = row < M;
                const __nv_bfloat16* src =
                    (tile ? Alo : Ahi) + (size_t)(ok ? row : 0) * K + k0c + seg * 8;
                cp16(dst, src, ok);
            } else {
                const __nv_bfloat16* src =
                    (tile == 3 ? Blo : Bhi) + (size_t)(n0 + r) * K + k0c + seg * 8;
                cp16(dst, src, true);
            }
        }
        CP_COMMIT();
    };

    load_stage(0, 0);

    for (int c = 0; c < nchunks; c++) {
        if (c + 1 < nchunks) load_stage(c + 1, (c + 1) & 1);
        if (c + 1 < nchunks) { CP_WAIT(1); } else { CP_WAIT(0); }
        __syncthreads();

        const uint32_t st = sb + (c & 1) * STG_B;
        const uint32_t sAhi = st, sAlo = st + TILE_B;
        const uint32_t sBhi = st + 2 * TILE_B, sBlo = st + 3 * TILE_B;

#pragma unroll
        for (int ks = 0; ks < 2; ks++) {
            const int kk = ks * 16;
            const int cb = (kk + aCol) * 2;

            uint32_t a[4][4];
#pragma unroll
            for (int mf = 0; mf < 4; mf++)
                ldmat4(a[mf][0], a[mf][1], a[mf][2], a[mf][3],
                       sAhi + tile_off(wm * 64 + mf * 16 + aRow, cb));
            uint32_t bh[2][4], bl[2][4];
#pragma unroll
            for (int bf = 0; bf < 2; bf++) {
                ldmat4(bh[bf][0], bh[bf][1], bh[bf][2], bh[bf][3],
                       sBhi + tile_off(wn * 32 + bf * 16 + aRow, cb));
                ldmat4(bl[bf][0], bl[bf][1], bl[bf][2], bl[bf][3],
                       sBlo + tile_off(wn * 32 + bf * 16 + aRow, cb));
            }
#pragma unroll
            for (int mf = 0; mf < 4; mf++)
#pragma unroll
                for (int nf = 0; nf < 4; nf++) {
                    mma16816(d[mf][nf][0], d[mf][nf][1], d[mf][nf][2], d[mf][nf][3],
                             a[mf][0], a[mf][1], a[mf][2], a[mf][3],
                             bh[nf >> 1][(nf & 1)], bh[nf >> 1][(nf & 1) + 2]);
                    mma16816(d[mf][nf][0], d[mf][nf][1], d[mf][nf][2], d[mf][nf][3],
                             a[mf][0], a[mf][1], a[mf][2], a[mf][3],
                             bl[nf >> 1][(nf & 1)], bl[nf >> 1][(nf & 1) + 2]);
                }
#pragma unroll
            for (int mf = 0; mf < 4; mf++)
                ldmat4(a[mf][0], a[mf][1], a[mf][2], a[mf][3],
                       sAlo + tile_off(wm * 64 + mf * 16 + aRow, cb));
#pragma unroll
            for (int mf = 0; mf < 4; mf++)
#pragma unroll
                for (int nf = 0; nf < 4; nf++)
                    mma16816(d[mf][nf][0], d[mf][nf][1], d[mf][nf][2], d[mf][nf][3],
                             a[mf][0], a[mf][1], a[mf][2], a[mf][3],
                             bh[nf >> 1][(nf & 1)], bh[nf >> 1][(nf & 1) + 2]);
        }
        __syncthreads();
    }

#pragma unroll
    for (int mf = 0; mf < 4; mf++) {
        int row = m0 + wm * 64 + mf * 16 + (lane >> 2);
#pragma unroll
        for (int half = 0; half < 2; half++) {
            int r = row + half * 8;
            if (r >= M) continue;
#pragma unroll
            for (int nf = 0; nf < 4; nf++) {
                int col = n0 + wn * 32 + nf * 8 + (lane & 3) * 2;
                float v0 = d[mf][nf][half * 2], v1 = d[mf][nf][half * 2 + 1];
                if (MODE >= 1) {
                    v0 += __ldg(bias + col);
                    v1 += __ldg(bias + col + 1);
                }
                if (MODE == 1) {
                    v0 = fmaxf(v0, 0.f); v1 = fmaxf(v1, 0.f);
                    __nv_bfloat16 h0, l0, h1, l1;
                    split1(v0, h0, l0); split1(v1, h1, l1);
                    __nv_bfloat162 hh; hh.x = h0; hh.y = h1;
                    __nv_bfloat162 ll; ll.x = l0; ll.y = l1;
                    *(__nv_bfloat162*)(Chi + (size_t)r * N + col) = hh;
                    *(__nv_bfloat162*)(Clo + (size_t)r * N + col) = ll;
                } else {
                    *(float2*)(Cf + (size_t)r * N + col) = make_float2(v0, v1);
                }
            }
        }
    }
}

// ---------------- graph part: sorted aggregation ----------------
// zero counters + bitmap + build Ctab + detect idx dtype, one launch
__global__ void prep_misc(int* __restrict__ deg, int* __restrict__ cnt,
                          const float* __restrict__ E1, const float* __restrict__ E2,
                          float* __restrict__ Ctab, const int* __restrict__ ei_words,
                          unsigned* __restrict__ maskbits)
{
    int i = blockIdx.x * 256 + threadIdx.x;
    if (i == 0) {
        int is64 = 1;
        for (int k = 1; k < 64; k += 2)
            if (ei_words[k] != 0) { is64 = 0; break; }
        g_is64 = is64;
    }
    if (i < NNODES) { deg[i] = 0; cnt[i] = 0; }
    if (i < (NNODES + 31) / 32) maskbits[i] = 0u;
    if (i < 10 * HIDDEN) {
        int c = i / HIDDEN, dd = i % HIDDEN;
        int r1 = (c == 9) ? 4 : (c % 3);
        int r2 = (c == 9) ? 0 : (c / 3);
        Ctab[i] = E1[r1 * HIDDEN + dd] + E2[r2 * HIDDEN + dd];
    }
}

__global__ void set_maskbits(const void* __restrict__ mask, unsigned* __restrict__ bits,
                             int nmask)
{
    int i = blockIdx.x * 256 + threadIdx.x;
    if (i >= nmask) return;
    int r = (int)load_idx(mask, i, g_is64);
    atomicOr(&bits[r >> 5], 1u << (r & 31));
}

__global__ void hist_dst(const void* __restrict__ ei, int* __restrict__ deg)
{
    int e = blockIdx.x * 256 + threadIdx.x;
    if (e >= NEDGES) return;
    int dst = (int)load_idx(ei, (long long)NEDGES + e, g_is64);
    atomicAdd(&deg[dst], 1);
}

// Exclusive prefix scan over NNODES ints (= 5000 int4). Single block, 1024 thr.
__global__ __launch_bounds__(1024)
void scan_deg(const int4* __restrict__ deg4, int4* __restrict__ off4)
{
    __shared__ int wsum[32];
    const int t = threadIdx.x, lane = t & 31, w = t >> 5;
    const int base = t * 5;
    int4 v[5];
    int sum = 0;
#pragma unroll
    for (int i = 0; i < 5; i++) {
        int idx = base + i;
        v[i] = (idx < 5000) ? deg4[idx] : make_int4(0, 0, 0, 0);
        sum += v[i].x + v[i].y + v[i].z + v[i].w;
    }
    int s = sum;
#pragma unroll
    for (int dlt = 1; dlt < 32; dlt <<= 1) {
        int o = __shfl_up_sync(0xffffffff, s, dlt);
        if (lane >= dlt) s += o;
    }
    if (lane == 31) wsum[w] = s;
    __syncthreads();
    if (w == 0) {
        int ws = (t < 32) ? wsum[t] : 0;
#pragma unroll
        for (int dlt = 1; dlt < 32; dlt <<= 1) {
            int o = __shfl_up_sync(0xffffffff, ws, dlt);
            if (lane >= dlt) ws += o;
        }
        if (t < 32) wsum[t] = ws;
    }
    __syncthreads();
    int pre = s - sum + (w > 0 ? wsum[w - 1] : 0);
#pragma unroll
    for (int i = 0; i < 5; i++) {
        int idx = base + i;
        if (idx < 5000) {
            int4 o;
            o.x = pre;            pre += v[i].x;
            o.y = pre;            pre += v[i].y;
            o.z = pre;            pre += v[i].z;
            o.w = pre;            pre += v[i].w;
            off4[idx] = o;
        }
    }
}

__global__ void scatter_edges(const void* __restrict__ ei, const void* __restrict__ ea,
                              const int* __restrict__ off, int* __restrict__ cnt,
                              int2* __restrict__ sorted)
{
    int e = blockIdx.x * 256 + threadIdx.x;
    if (e >= NEDGES) return;
    const int is64 = g_is64;
    int src = (int)load_idx(ei, e, is64);
    int dst = (int)load_idx(ei, (long long)NEDGES + e, is64);
    int a0  = (int)load_idx(ea, 2LL * e, is64);
    int a1  = (int)load_idx(ea, 2LL * e + 1, is64);
    int pos = off[dst] + atomicAdd(&cnt[dst], 1);
    sorted[pos] = make_int2(src, a0 + 3 * a1);
}

// One 64-thread block per node: register accumulation + mask-predicated h1 terms
// + fused bf16 hi/lo split. (Masked rows contribute 0 for the h1 part only.)
__global__ __launch_bounds__(64)
void aggregate(const float* __restrict__ h1, const int2* __restrict__ sorted,
               const int* __restrict__ off, const float* __restrict__ Ctab,
               const unsigned* __restrict__ bits,
               __nv_bfloat16* __restrict__ aghi, __nv_bfloat16* __restrict__ aglo)
{
    const int n = blockIdx.x;
    const int t = threadIdx.x;
    const int s0 = off[n];
    const int s1 = (n == NNODES - 1) ? NEDGES : off[n + 1];

    float selfS = ((bits[n >> 5] >> (n & 31)) & 1u) ? 0.f : 1.f;
    float4 hv = ((const float4*)(h1 + (size_t)n * HIDDEN))[t];
    float4 cs  = ((const float4*)(Ctab + 9 * HIDDEN))[t];
    float4 acc;
    acc.x = fmaf(hv.x, selfS, cs.x);
    acc.y = fmaf(hv.y, selfS, cs.y);
    acc.z = fmaf(hv.z, selfS, cs.z);
    acc.w = fmaf(hv.w, selfS, cs.w);

    int p = s0;
    for (; p + 1 < s1; p += 2) {
        int2 r0 = __ldg(&sorted[p]);
        int2 r1 = __ldg(&sorted[p + 1]);
        float sc0 = ((bits[r0.x >> 5] >> (r0.x & 31)) & 1u) ? 0.f : 1.f;
        float sc1 = ((bits[r1.x >> 5] >> (r1.x & 31)) & 1u) ? 0.f : 1.f;
        float4 x0 = ((const float4*)(h1 + (size_t)r0.x * HIDDEN))[t];
        float4 c0 = ((const float4*)(Ctab + r0.y * HIDDEN))[t];
        float4 x1 = ((const float4*)(h1 + (size_t)r1.x * HIDDEN))[t];
        float4 c1 = ((const float4*)(Ctab + r1.y * HIDDEN))[t];
        acc.x += fmaf(x0.x, sc0, c0.x); acc.y += fmaf(x0.y, sc0, c0.y);
        acc.z += fmaf(x0.z, sc0, c0.z); acc.w += fmaf(x0.w, sc0, c0.w);
        acc.x += fmaf(x1.x, sc1, c1.x); acc.y += fmaf(x1.y, sc1, c1.y);
        acc.z += fmaf(x1.z, sc1, c1.z); acc.w += fmaf(x1.w, sc1, c1.w);
    }
    if (p < s1) {
        int2 rec = __ldg(&sorted[p]);
        float sc = ((bits[rec.x >> 5] >> (rec.x & 31)) & 1u) ? 0.f : 1.f;
        float4 xv = ((const float4*)(h1 + (size_t)rec.x * HIDDEN))[t];
        float4 cv = ((const float4*)(Ctab + rec.y * HIDDEN))[t];
        acc.x += fmaf(xv.x, sc, cv.x); acc.y += fmaf(xv.y, sc, cv.y);
        acc.z += fmaf(xv.z, sc, cv.z); acc.w += fmaf(xv.w, sc, cv.w);
    }

    __nv_bfloat16 h[4], l[4];
    split1(acc.x, h[0], l[0]); split1(acc.y, h[1], l[1]);
    split1(acc.z, h[2], l[2]); split1(acc.w, h[3], l[3]);
    ((uint2*)(aghi + (size_t)n * HIDDEN))[t] = *(uint2*)h;
    ((uint2*)(aglo + (size_t)n * HIDDEN))[t] = *(uint2*)l;
}

extern "C" void kernel_launch(void* const* d_in, const int* in_sizes, int n_in,
                              void* d_out, int out_size)
{
    const float* x     = (const float*)d_in[0];
    const void*  ei    = d_in[1];
    const void*  ea    = d_in[2];
    const void*  mask  = d_in[3];
    const float* pa    = (const float*)d_in[4];
    const float* W_enc = (const float*)d_in[5];
    const float* E1    = (const float*)d_in[6];
    const float* E2    = (const float*)d_in[7];
    const float* W1    = (const float*)d_in[8];
    const float* b1    = (const float*)d_in[9];
    const float* W2    = (const float*)d_in[10];
    const float* b2    = (const float*)d_in[11];
    float* out = (float*)d_out;

    float *h1, *Ctab;
    int *deg, *cnt, *off;
    int2 *sorted;
    unsigned *maskbits;
    __nv_bfloat16 *xhi, *xlo, *aghi, *aglo, *h2hi, *h2lo;
    __nv_bfloat16 *Wehi, *Welo, *W1hi, *W1lo, *W2hi, *W2lo;
    cudaGetSymbolAddress((void**)&h1,     g_h1);
    cudaGetSymbolAddress((void**)&Ctab,   g_Ctab);
    cudaGetSymbolAddress((void**)&deg,    g_deg);
    cudaGetSymbolAddress((void**)&cnt,    g_cnt);
    cudaGetSymbolAddress((void**)&off,    g_off);
    cudaGetSymbolAddress((void**)&sorted, g_sorted);
    cudaGetSymbolAddress((void**)&maskbits, g_maskbits);
    cudaGetSymbolAddress((void**)&xhi,  g_x_hi);
    cudaGetSymbolAddress((void**)&xlo,  g_x_lo);
    cudaGetSymbolAddress((void**)&aghi, g_ag_hi);
    cudaGetSymbolAddress((void**)&aglo, g_ag_lo);
    cudaGetSymbolAddress((void**)&h2hi, g_h2_hi);
    cudaGetSymbolAddress((void**)&h2lo, g_h2_lo);
    cudaGetSymbolAddress((void**)&Wehi, g_We_hi);
    cudaGetSymbolAddress((void**)&Welo, g_We_lo);
    cudaGetSymbolAddress((void**)&W1hi, g_W1_hi);
    cudaGetSymbolAddress((void**)&W1lo, g_W1_lo);
    cudaGetSymbolAddress((void**)&W2hi, g_W2_hi);
    cudaGetSymbolAddress((void**)&W2lo, g_W2_lo);

    const int SMEM_SZ = 2 * STG_B;   // 65536 -> 2 CTAs/SM
    cudaFuncSetAttribute(gemm_mma<0>, cudaFuncAttributeMaxDynamicSharedMemorySize, SMEM_SZ);
    cudaFuncSetAttribute(gemm_mma<1>, cudaFuncAttributeMaxDynamicSharedMemorySize, SMEM_SZ);
    cudaFuncSetAttribute(gemm_mma<2>, cudaFuncAttributeMaxDynamicSharedMemorySize, SMEM_SZ);

    const int MB = (NNODES + 127) / 128;   // 157
    const int EB = (NEDGES + 255) / 256;   // 1250

    // ---- fork: graph-prep chain + weight split on side stream ----
    cudaEventRecord(g_evFork, 0);
    cudaStreamWaitEvent(g_s2, g_evFork, 0);
    prep_misc<<<(NNODES + 255) / 256, 256, 0, g_s2>>>(deg, cnt, E1, E2, Ctab,
                                                      (const int*)ei, maskbits);
    set_maskbits<<<(2000 + 255) / 256, 256, 0, g_s2>>>(mask, maskbits, 2000);
    hist_dst<<<EB, 256, 0, g_s2>>>(ei, deg);
    scan_deg<<<1, 1024, 0, g_s2>>>((const int4*)deg, (int4*)off);
    scatter_edges<<<EB, 256, 0, g_s2>>>(ei, ea, off, cnt, sorted);
    split_weights<<<(81920 + 255) / 256, 256, 0, g_s2>>>(W_enc, W1, W2,
                                                Wehi, Welo, W1hi, W1lo, W2hi, W2lo);
    cudaEventRecord(g_evJoin, g_s2);

    // ---- main stream: split_x, then join (GEMM1 needs weights) ----
    split_f32<1><<<(NNODES * HIDDEN / 4 + 255) / 256, 256>>>(x, xhi, xlo, NNODES * HIDDEN / 4, pa);
    cudaStreamWaitEvent(0, g_evJoin, 0);
    gemm_mma<0><<<dim3(HIDDEN / 128, MB), 256, SMEM_SZ>>>(
        xhi, xlo, Wehi, Welo, nullptr, h1, nullptr, nullptr, NNODES, HIDDEN, HIDDEN);

    // ---- aggregation (mask fused) + GIN MLP ----
    aggregate<<<NNODES, 64>>>(h1, sorted, off, Ctab, maskbits, aghi, aglo);

    gemm_mma<1><<<dim3(2 * HIDDEN / 128, MB), 256, SMEM_SZ>>>(
        aghi, aglo, W1hi, W1lo, b1, nullptr, h2hi, h2lo, NNODES, 2 * HIDDEN, HIDDEN);

    gemm_mma<2><<<dim3(HIDDEN / 128, MB), 256, SMEM_SZ>>>(
        h2hi, h2lo, W2hi, W2lo, b2, out, nullptr, nullptr, NNODES, HIDDEN, 2 * HIDDEN);
}